// round 3
// baseline (speedup 1.0000x reference)
#include <cuda_runtime.h>
#include <cuda_bf16.h>
#include <cstdint>

// Decoder (Conv-TasNet): out = overlap_add( (mixture_w * est_mask)^T @ W^T, step=L/2 )
// mixture_w/est_mask [B, N, K] f32, W [L, N] f32, out [B, T] f32
// B=4, N=512, K=16000, L=16, step=8, T = 8*(K-1)+16 = 128008

#define DEC_B 4
#define DEC_N 512
#define DEC_K 16000
#define DEC_L 16
#define DEC_STEP 8
#define DEC_T (DEC_STEP * (DEC_K - 1) + DEC_L)   // 128008

#define TPB 128
#define NSPLIT 8
#define NCHUNK (DEC_N / NSPLIT)      // 64
#define KPT 2                         // frames per thread (float2 along k)
#define ACC_SPAN (DEC_STEP * KPT + DEC_STEP)  // 24 unique out positions per thread

__global__ __launch_bounds__(TPB)
void decoder_kernel(const float* __restrict__ mw,
                    const float* __restrict__ em,
                    const float* __restrict__ W,
                    float* __restrict__ out)
{
    // Stage this block's N-chunk of W transposed: Ws[n_local][l], 4 KB.
    __shared__ float Ws[NCHUNK * DEC_L];
    const int nb = blockIdx.z * NCHUNK;
    for (int i = threadIdx.x; i < NCHUNK * DEC_L; i += TPB) {
        int n = i >> 4;
        int l = i & 15;
        Ws[i] = W[l * DEC_N + nb + n];
    }
    __syncthreads();

    const int b  = blockIdx.y;
    const int k0 = (blockIdx.x * TPB + threadIdx.x) * KPT;
    if (k0 >= DEC_K) return;   // K even, so k0 valid => k0+1 valid

    const size_t base = (size_t)b * DEC_N * DEC_K + (size_t)nb * DEC_K + k0;
    const float2* __restrict__ mwp = reinterpret_cast<const float2*>(mw + base);
    const float2* __restrict__ emp = reinterpret_cast<const float2*>(em + base);

    // Frames k0 and k0+1 overlap by 8: acc[0..15] <- frame0, acc[8..23] <- frame1.
    float acc[ACC_SPAN];
#pragma unroll
    for (int i = 0; i < ACC_SPAN; ++i) acc[i] = 0.0f;

#pragma unroll 4
    for (int n = 0; n < NCHUNK; ++n) {
        // coalesced + streaming (each input byte read exactly once chip-wide)
        float2 m = __ldcs(&mwp[(size_t)n * (DEC_K / 2)]);
        float2 e = __ldcs(&emp[(size_t)n * (DEC_K / 2)]);
        float p0 = m.x * e.x;
        float p1 = m.y * e.y;

        const float4* w4 = reinterpret_cast<const float4*>(&Ws[n * DEC_L]);
        float4 w0 = w4[0];
        float4 w1 = w4[1];
        float4 w2 = w4[2];
        float4 w3 = w4[3];

        acc[0]  = fmaf(p0, w0.x, acc[0]);
        acc[1]  = fmaf(p0, w0.y, acc[1]);
        acc[2]  = fmaf(p0, w0.z, acc[2]);
        acc[3]  = fmaf(p0, w0.w, acc[3]);
        acc[4]  = fmaf(p0, w1.x, acc[4]);
        acc[5]  = fmaf(p0, w1.y, acc[5]);
        acc[6]  = fmaf(p0, w1.z, acc[6]);
        acc[7]  = fmaf(p0, w1.w, acc[7]);
        acc[8]  = fmaf(p0, w2.x, acc[8]);
        acc[9]  = fmaf(p0, w2.y, acc[9]);
        acc[10] = fmaf(p0, w2.z, acc[10]);
        acc[11] = fmaf(p0, w2.w, acc[11]);
        acc[12] = fmaf(p0, w3.x, acc[12]);
        acc[13] = fmaf(p0, w3.y, acc[13]);
        acc[14] = fmaf(p0, w3.z, acc[14]);
        acc[15] = fmaf(p0, w3.w, acc[15]);

        acc[8]  = fmaf(p1, w0.x, acc[8]);
        acc[9]  = fmaf(p1, w0.y, acc[9]);
        acc[10] = fmaf(p1, w0.z, acc[10]);
        acc[11] = fmaf(p1, w0.w, acc[11]);
        acc[12] = fmaf(p1, w1.x, acc[12]);
        acc[13] = fmaf(p1, w1.y, acc[13]);
        acc[14] = fmaf(p1, w1.z, acc[14]);
        acc[15] = fmaf(p1, w1.w, acc[15]);
        acc[16] = fmaf(p1, w2.x, acc[16]);
        acc[17] = fmaf(p1, w2.y, acc[17]);
        acc[18] = fmaf(p1, w2.z, acc[18]);
        acc[19] = fmaf(p1, w2.w, acc[19]);
        acc[20] = fmaf(p1, w3.x, acc[20]);
        acc[21] = fmaf(p1, w3.y, acc[21]);
        acc[22] = fmaf(p1, w3.z, acc[22]);
        acc[23] = fmaf(p1, w3.w, acc[23]);
    }

    // Scatter-add the 24 unique positions covered by frames k0, k0+1.
    // Each out element receives <= 2*NSPLIT = 16 fp32 contributions (atomic).
    float* __restrict__ op = out + (size_t)b * DEC_T + (size_t)k0 * DEC_STEP;
#pragma unroll
    for (int i = 0; i < ACC_SPAN; ++i) {
        atomicAdd(&op[i], acc[i]);
    }
}

extern "C" void kernel_launch(void* const* d_in, const int* in_sizes, int n_in,
                              void* d_out, int out_size)
{
    const float* mixture_w = (const float*)d_in[0];  // [B, N, K]
    const float* est_mask  = (const float*)d_in[1];  // [B, N, K]
    const float* W         = (const float*)d_in[2];  // [L, N]
    float* out = (float*)d_out;                       // [B, T]

    cudaMemsetAsync(out, 0, (size_t)out_size * sizeof(float), 0);

    dim3 grid((DEC_K + TPB * KPT - 1) / (TPB * KPT), DEC_B, NSPLIT);  // (63, 4, 8)
    decoder_kernel<<<grid, TPB>>>(mixture_w, est_mask, W, out);
}

// round 4
// speedup vs baseline: 1.0483x; 1.0483x over previous
#include <cuda_runtime.h>
#include <cuda_bf16.h>
#include <cstdint>

// Decoder (Conv-TasNet): out = overlap_add( (mixture_w * est_mask)^T @ W^T, step=L/2 )
// mixture_w/est_mask [B, N, K] f32, W [L, N] f32, out [B, T] f32
// B=4, N=512, K=16000, L=16, step=8, T = 8*(K-1)+16 = 128008

#define DEC_B 4
#define DEC_N 512
#define DEC_K 16000
#define DEC_L 16
#define DEC_STEP 8
#define DEC_T (DEC_STEP * (DEC_K - 1) + DEC_L)   // 128008

#define TPB 128
#define NSPLIT 4
#define NCHUNK (DEC_N / NSPLIT)      // 128
#define KPT 2                         // frames per thread (float2 along k)
#define ACC_SPAN (DEC_STEP * KPT + DEC_STEP)  // 24 unique out positions per thread
#define PIPE 4                        // n-iterations per pipeline stage

// One n-step: p0 feeds acc[0..15], p1 feeds acc[8..23] (frames overlap by 8).
__device__ __forceinline__ void frame_fma(float* __restrict__ acc,
                                          float2 m, float2 e,
                                          const float* __restrict__ wrow)
{
    float p0 = m.x * e.x;
    float p1 = m.y * e.y;
    const float4* w4 = reinterpret_cast<const float4*>(wrow);
    float4 w0 = w4[0];
    float4 w1 = w4[1];
    float4 w2 = w4[2];
    float4 w3 = w4[3];

    acc[0]  = fmaf(p0, w0.x, acc[0]);
    acc[1]  = fmaf(p0, w0.y, acc[1]);
    acc[2]  = fmaf(p0, w0.z, acc[2]);
    acc[3]  = fmaf(p0, w0.w, acc[3]);
    acc[4]  = fmaf(p0, w1.x, acc[4]);
    acc[5]  = fmaf(p0, w1.y, acc[5]);
    acc[6]  = fmaf(p0, w1.z, acc[6]);
    acc[7]  = fmaf(p0, w1.w, acc[7]);
    acc[8]  = fmaf(p0, w2.x, acc[8]);
    acc[9]  = fmaf(p0, w2.y, acc[9]);
    acc[10] = fmaf(p0, w2.z, acc[10]);
    acc[11] = fmaf(p0, w2.w, acc[11]);
    acc[12] = fmaf(p0, w3.x, acc[12]);
    acc[13] = fmaf(p0, w3.y, acc[13]);
    acc[14] = fmaf(p0, w3.z, acc[14]);
    acc[15] = fmaf(p0, w3.w, acc[15]);

    acc[8]  = fmaf(p1, w0.x, acc[8]);
    acc[9]  = fmaf(p1, w0.y, acc[9]);
    acc[10] = fmaf(p1, w0.z, acc[10]);
    acc[11] = fmaf(p1, w0.w, acc[11]);
    acc[12] = fmaf(p1, w1.x, acc[12]);
    acc[13] = fmaf(p1, w1.y, acc[13]);
    acc[14] = fmaf(p1, w1.z, acc[14]);
    acc[15] = fmaf(p1, w1.w, acc[15]);
    acc[16] = fmaf(p1, w2.x, acc[16]);
    acc[17] = fmaf(p1, w2.y, acc[17]);
    acc[18] = fmaf(p1, w2.z, acc[18]);
    acc[19] = fmaf(p1, w2.w, acc[19]);
    acc[20] = fmaf(p1, w3.x, acc[20]);
    acc[21] = fmaf(p1, w3.y, acc[21]);
    acc[22] = fmaf(p1, w3.z, acc[22]);
    acc[23] = fmaf(p1, w3.w, acc[23]);
}

__global__ __launch_bounds__(TPB)
void decoder_kernel(const float* __restrict__ mw,
                    const float* __restrict__ em,
                    const float* __restrict__ W,
                    float* __restrict__ out)
{
    // Stage this block's N-chunk of W transposed: Ws[n_local][l], 8 KB.
    __shared__ float Ws[NCHUNK * DEC_L];
    const int nb = blockIdx.z * NCHUNK;
    for (int i = threadIdx.x; i < NCHUNK * DEC_L; i += TPB) {
        int n = i >> 4;
        int l = i & 15;
        Ws[i] = W[l * DEC_N + nb + n];
    }
    __syncthreads();

    const int b  = blockIdx.y;
    const int k0 = (blockIdx.x * TPB + threadIdx.x) * KPT;
    if (k0 >= DEC_K) return;   // K even

    const size_t base = (size_t)b * DEC_N * DEC_K + (size_t)nb * DEC_K + k0;
    const float2* __restrict__ mwp = reinterpret_cast<const float2*>(mw + base);
    const float2* __restrict__ emp = reinterpret_cast<const float2*>(em + base);
    const size_t kstride = DEC_K / 2;   // float2 stride between n rows

    float acc[ACC_SPAN];
#pragma unroll
    for (int i = 0; i < ACC_SPAN; ++i) acc[i] = 0.0f;

    // Software-pipelined: two PIPE-deep buffers; 2*PIPE LDG.64 in flight while
    // the other buffer's 4x32 FMAs execute.
    float2 ma[PIPE], ea[PIPE], mb[PIPE], eb[PIPE];

#pragma unroll
    for (int j = 0; j < PIPE; ++j) {
        ma[j] = __ldcs(&mwp[(size_t)j * kstride]);
        ea[j] = __ldcs(&emp[(size_t)j * kstride]);
    }

#pragma unroll 2
    for (int n = 0; n < NCHUNK; n += 2 * PIPE) {
        // prefetch B = n+4 .. n+7
#pragma unroll
        for (int j = 0; j < PIPE; ++j) {
            mb[j] = __ldcs(&mwp[(size_t)(n + PIPE + j) * kstride]);
            eb[j] = __ldcs(&emp[(size_t)(n + PIPE + j) * kstride]);
        }
        // compute A = n .. n+3
#pragma unroll
        for (int j = 0; j < PIPE; ++j)
            frame_fma(acc, ma[j], ea[j], &Ws[(n + j) * DEC_L]);

        // prefetch A = n+8 .. n+11 (skip past end; NCHUNK % (2*PIPE) == 0)
        if (n + 2 * PIPE < NCHUNK) {
#pragma unroll
            for (int j = 0; j < PIPE; ++j) {
                ma[j] = __ldcs(&mwp[(size_t)(n + 2 * PIPE + j) * kstride]);
                ea[j] = __ldcs(&emp[(size_t)(n + 2 * PIPE + j) * kstride]);
            }
        }
        // compute B = n+4 .. n+7
#pragma unroll
        for (int j = 0; j < PIPE; ++j)
            frame_fma(acc, mb[j], eb[j], &Ws[(n + PIPE + j) * DEC_L]);
    }

    // Scatter-add the 24 unique positions covered by frames k0, k0+1.
    // Each out element receives <= 2*NSPLIT = 8 fp32 contributions (atomic).
    float* __restrict__ op = out + (size_t)b * DEC_T + (size_t)k0 * DEC_STEP;
#pragma unroll
    for (int i = 0; i < ACC_SPAN; ++i) {
        atomicAdd(&op[i], acc[i]);
    }
}

extern "C" void kernel_launch(void* const* d_in, const int* in_sizes, int n_in,
                              void* d_out, int out_size)
{
    const float* mixture_w = (const float*)d_in[0];  // [B, N, K]
    const float* est_mask  = (const float*)d_in[1];  // [B, N, K]
    const float* W         = (const float*)d_in[2];  // [L, N]
    float* out = (float*)d_out;                       // [B, T]

    cudaMemsetAsync(out, 0, (size_t)out_size * sizeof(float), 0);

    dim3 grid((DEC_K + TPB * KPT - 1) / (TPB * KPT), DEC_B, NSPLIT);  // (63, 4, 4)
    decoder_kernel<<<grid, TPB>>>(mixture_w, est_mask, W, out);
}